// round 16
// baseline (speedup 1.0000x reference)
#include <cuda_runtime.h>
#include <cuda_bf16.h>

#define Nn 100000
#define Ee 1600000
#define Hh 128

// ---------------- scratch (device globals; no allocs allowed) ----------------
__device__ float g_xs[(size_t)Nn * Hh];    // xs = in @ W_src      (51.2 MB)
__device__ float g_S [(size_t)Nn * Hh];    // unnormalized msg sum (51.2 MB)
__device__ float g_h [(size_t)Nn * Hh];    // layer output         (51.2 MB)
__device__ float g_as[Nn];
__device__ float g_ad[Nn];
__device__ float g_denom[Nn];
__device__ float g_vd[Hh];                 // W_dst @ att_dst

// ---------------- f32x2 packed-FMA helpers (sm_103a FFMA2) ----------------
__device__ __forceinline__ unsigned long long fma2(unsigned long long a,
                                                   unsigned long long b,
                                                   unsigned long long c) {
    unsigned long long d;
    asm("fma.rn.f32x2 %0, %1, %2, %3;" : "=l"(d) : "l"(a), "l"(b), "l"(c));
    return d;
}
__device__ __forceinline__ unsigned long long pack2(float x) {
    unsigned long long d;
    asm("mov.b64 %0, {%1, %2};" : "=l"(d) : "f"(x), "f"(x));
    return d;
}
__device__ __forceinline__ void unpack2(unsigned long long v, float& lo, float& hi) {
    asm("mov.b64 {%0, %1}, %2;" : "=f"(lo), "=f"(hi) : "l"(v));
}

// ---------------- vd = W_dst @ att_dst : warp per output ----------------
__global__ void k_vd(const float* __restrict__ Wd, const float* __restrict__ attd) {
    int w = (blockIdx.x * 256 + threadIdx.x) >> 5;
    int lane = threadIdx.x & 31;
    if (w >= Hh) return;
    float4 a = *(const float4*)&Wd[w * Hh + lane * 4];
    float4 u = *(const float4*)&attd[lane * 4];
    float s = a.x * u.x + a.y * u.y + a.z * u.z + a.w * u.w;
    #pragma unroll
    for (int o = 16; o; o >>= 1) s += __shfl_xor_sync(0xffffffffu, s, o);
    if (lane == 0) g_vd[w] = s;
}

// ---------------- GEMM: g_xs = A @ W   (A: [N,128] fp32, W: [128,128]) ----------
// 64 rows x 128 cols per 256-thread block. W + x-tile in SMEM, FFMA2 accumulators.
#define GEMM_SMEM ((128 * 128 + 64 * 132) * 4)
__global__ __launch_bounds__(256) void k_gemm(const float* __restrict__ Aext,
                                              int use_h,
                                              const float* __restrict__ Wg) {
    extern __shared__ float sm[];
    float* Wsm = sm;              // 128*128
    float* Xsm = sm + 128 * 128;  // 64 * 132 (padded)
    const int XS = 132;
    const float* A = use_h ? (const float*)g_h : Aext;
    int t = threadIdx.x;

    #pragma unroll
    for (int i = 0; i < 16; i++) {
        int idx = (t + i * 256) * 4;
        *(float4*)&Wsm[idx] = *(const float4*)&Wg[idx];
    }
    int row0 = blockIdx.x * 64;
    #pragma unroll
    for (int i = 0; i < 8; i++) {
        int idx = t + i * 256;            // 0..2047
        int r = idx >> 5, c4 = idx & 31;
        float4 v = make_float4(0.f, 0.f, 0.f, 0.f);
        int gr = row0 + r;
        if (gr < Nn) v = *(const float4*)&A[(size_t)gr * 128 + c4 * 4];
        *(float4*)&Xsm[r * XS + c4 * 4] = v;
    }
    __syncthreads();

    int tx = t & 15, ty = t >> 4;
    const float* xbase = &Xsm[ty * 4 * XS];
    const float* wbase = &Wsm[tx * 8];

    unsigned long long acc[4][4];
    #pragma unroll
    for (int i = 0; i < 4; i++)
        #pragma unroll
        for (int p = 0; p < 4; p++) acc[i][p] = 0ull;

    #pragma unroll 8
    for (int k = 0; k < 128; k++) {
        ulonglong2 w01 = *(const ulonglong2*)&wbase[k * 128];
        ulonglong2 w23 = *(const ulonglong2*)&wbase[k * 128 + 4];
        unsigned long long wp0 = w01.x, wp1 = w01.y, wp2 = w23.x, wp3 = w23.y;
        #pragma unroll
        for (int i = 0; i < 4; i++) {
            unsigned long long xp = pack2(xbase[i * XS + k]);
            acc[i][0] = fma2(xp, wp0, acc[i][0]);
            acc[i][1] = fma2(xp, wp1, acc[i][1]);
            acc[i][2] = fma2(xp, wp2, acc[i][2]);
            acc[i][3] = fma2(xp, wp3, acc[i][3]);
        }
    }

    #pragma unroll
    for (int i = 0; i < 4; i++) {
        int gr = row0 + ty * 4 + i;
        if (gr < Nn) {
            float o[8];
            #pragma unroll
            for (int p = 0; p < 4; p++) unpack2(acc[i][p], o[2 * p], o[2 * p + 1]);
            float* dstp = &g_xs[(size_t)gr * 128 + tx * 8];
            *(float4*)&dstp[0] = make_float4(o[0], o[1], o[2], o[3]);
            *(float4*)&dstp[4] = make_float4(o[4], o[5], o[6], o[7]);
        }
    }
}

// ---------------- a_s = xs @ att_src ; a_d = in @ vd : warp per row ----------
__global__ __launch_bounds__(256) void k_rowdot(const float* __restrict__ inext,
                                                int use_h,
                                                const float* __restrict__ atts) {
    int t = blockIdx.x * 256 + threadIdx.x;
    int w = t >> 5, lane = t & 31;
    if (w >= Nn) return;
    const float* in = use_h ? (const float*)g_h : inext;
    float4 a = *(const float4*)&g_xs[(size_t)w * 128 + lane * 4];
    float4 u = *(const float4*)&atts[lane * 4];
    float s1 = a.x * u.x + a.y * u.y + a.z * u.z + a.w * u.w;
    float4 b = *(const float4*)&in[(size_t)w * 128 + lane * 4];
    float4 v = *(const float4*)&g_vd[lane * 4];
    float s2 = b.x * v.x + b.y * v.y + b.z * v.z + b.w * v.w;
    #pragma unroll
    for (int o = 16; o; o >>= 1) {
        s1 += __shfl_xor_sync(0xffffffffu, s1, o);
        s2 += __shfl_xor_sync(0xffffffffu, s2, o);
    }
    if (lane == 0) { g_as[w] = s1; g_ad[w] = s2; }
}

// ---------------- zero S + denom ----------------
__global__ void k_zero() {
    int t = blockIdx.x * 256 + threadIdx.x;
    if (t < Nn * 32)
        *(float4*)&g_S[(size_t)t * 4] = make_float4(0.f, 0.f, 0.f, 0.f);
    if (t < Nn) g_denom[t] = 0.f;
}

// ---------------- fused edge kernel: softmax numerator + scatter ----------------
// warp per edge, 4 edges per warp. exp without max-shift (shift-invariant; |e| small).
__global__ __launch_bounds__(256) void k_edge(const int* __restrict__ src,
                                              const int* __restrict__ dst) {
    int wid = (blockIdx.x * 256 + threadIdx.x) >> 5;
    int lane = threadIdx.x & 31;
    int e0 = wid * 4;
    #pragma unroll
    for (int j = 0; j < 4; j++) {
        int e = e0 + j;                  // grid sized so e < Ee always
        int s = src[e], d = dst[e];
        float t = g_as[s] + g_ad[d];
        t = t > 0.f ? t : 0.2f * t;      // leaky_relu(0.2)
        float ex = expf(t);
        if (lane == 0) atomicAdd(&g_denom[d], ex);
        float4 v = *(const float4*)&g_xs[(size_t)s * 128 + lane * 4];
        float* p = &g_S[(size_t)d * 128 + lane * 4];
        asm volatile("red.global.add.v4.f32 [%0], {%1,%2,%3,%4};"
                     :: "l"(p), "f"(v.x * ex), "f"(v.y * ex),
                        "f"(v.z * ex), "f"(v.w * ex)
                     : "memory");
    }
}

// ---------------- node epilogue: h = relu(S/(denom+eps) + bias) ----------------
__global__ void k_node(const float* __restrict__ bias) {
    int t = blockIdx.x * 256 + threadIdx.x;
    if (t >= Nn * 32) return;
    int n = t >> 5, j = t & 31;
    float inv = 1.0f / (g_denom[n] + 1e-16f);
    float4 s = *(const float4*)&g_S[(size_t)t * 4];
    float4 b = *(const float4*)&bias[j * 4];
    float4 o;
    o.x = fmaxf(fmaf(s.x, inv, b.x), 0.f);
    o.y = fmaxf(fmaf(s.y, inv, b.y), 0.f);
    o.z = fmaxf(fmaf(s.z, inv, b.z), 0.f);
    o.w = fmaxf(fmaf(s.w, inv, b.w), 0.f);
    *(float4*)&g_h[(size_t)t * 4] = o;
}

// ---------------- final projection: out = h @ Wl + bl  (O=2) ----------------
__global__ __launch_bounds__(256) void k_final(const float* __restrict__ Wl,
                                               const float* __restrict__ bl,
                                               float* __restrict__ out) {
    __shared__ float wl[256];
    wl[threadIdx.x] = Wl[threadIdx.x];
    __syncthreads();
    int t = blockIdx.x * 256 + threadIdx.x;
    int w = t >> 5, lane = t & 31;
    if (w >= Nn) return;
    float4 v = *(const float4*)&g_h[(size_t)w * 128 + lane * 4];
    int h0 = lane * 4;
    float s0 = v.x * wl[h0 * 2 + 0] + v.y * wl[h0 * 2 + 2] +
               v.z * wl[h0 * 2 + 4] + v.w * wl[h0 * 2 + 6];
    float s1 = v.x * wl[h0 * 2 + 1] + v.y * wl[h0 * 2 + 3] +
               v.z * wl[h0 * 2 + 5] + v.w * wl[h0 * 2 + 7];
    #pragma unroll
    for (int o = 16; o; o >>= 1) {
        s0 += __shfl_xor_sync(0xffffffffu, s0, o);
        s1 += __shfl_xor_sync(0xffffffffu, s1, o);
    }
    if (lane == 0) {
        out[w * 2 + 0] = s0 + bl[0];
        out[w * 2 + 1] = s1 + bl[1];
    }
}

// ---------------- launch ----------------
extern "C" void kernel_launch(void* const* d_in, const int* in_sizes, int n_in,
                              void* d_out, int out_size) {
    const float* x   = (const float*)d_in[0];
    const int*   ei  = (const int*)d_in[1];
    const float* W1s = (const float*)d_in[2];
    const float* W1d = (const float*)d_in[3];
    const float* a1s = (const float*)d_in[4];
    const float* a1d = (const float*)d_in[5];
    const float* b1  = (const float*)d_in[6];
    const float* W2s = (const float*)d_in[7];
    const float* W2d = (const float*)d_in[8];
    const float* a2s = (const float*)d_in[9];
    const float* a2d = (const float*)d_in[10];
    const float* b2  = (const float*)d_in[11];
    const float* Wl  = (const float*)d_in[12];
    const float* bl  = (const float*)d_in[13];
    float* out = (float*)d_out;
    const int* src = ei;
    const int* dst = ei + Ee;

    cudaFuncSetAttribute(k_gemm, cudaFuncAttributeMaxDynamicSharedMemorySize,
                         GEMM_SMEM);

    const int GB   = (Nn + 63) / 64;          // gemm blocks: 1563
    const int RB   = (Nn * 32 + 255) / 256;   // warp-per-row / elem kernels: 12500
    const int EB   = Ee / (8 * 4);            // edge blocks: 50000 (exact)

    // ---- layer 1 ----
    k_vd    <<<16, 256>>>(W1d, a1d);
    k_gemm  <<<GB, 256, GEMM_SMEM>>>(x, 0, W1s);
    k_rowdot<<<RB, 256>>>(x, 0, a1s);
    k_zero  <<<RB, 256>>>();
    k_edge  <<<EB, 256>>>(src, dst);
    k_node  <<<RB, 256>>>(b1);

    // ---- layer 2 ----
    k_vd    <<<16, 256>>>(W2d, a2d);
    k_gemm  <<<GB, 256, GEMM_SMEM>>>(nullptr, 1, W2s);
    k_rowdot<<<RB, 256>>>(nullptr, 1, a2s);
    k_zero  <<<RB, 256>>>();
    k_edge  <<<EB, 256>>>(src, dst);
    k_node  <<<RB, 256>>>(b2);

    // ---- final linear ----
    k_final <<<RB, 256>>>(Wl, bl, out);
}

// round 17
// speedup vs baseline: 1.0057x; 1.0057x over previous
#include <cuda_runtime.h>
#include <cuda_bf16.h>

#define Nn 100000
#define Ee 1600000
#define Hh 128

// ---------------- scratch (device globals; no allocs allowed) ----------------
__device__ float g_xs[(size_t)Nn * Hh];    // xs = in @ W_src      (51.2 MB)
__device__ float g_S [(size_t)Nn * Hh];    // unnormalized msg sum (51.2 MB)
__device__ float g_h [(size_t)Nn * Hh];    // layer output         (51.2 MB)
__device__ float g_as[Nn];
__device__ float g_ad[Nn];
__device__ float g_denom[Nn];
__device__ float g_vd[Hh];                 // W_dst @ att_dst

// ---------------- f32x2 packed-FMA helpers (sm_103a FFMA2) ----------------
__device__ __forceinline__ unsigned long long fma2(unsigned long long a,
                                                   unsigned long long b,
                                                   unsigned long long c) {
    unsigned long long d;
    asm("fma.rn.f32x2 %0, %1, %2, %3;" : "=l"(d) : "l"(a), "l"(b), "l"(c));
    return d;
}
__device__ __forceinline__ unsigned long long pack2(float x) {
    unsigned long long d;
    asm("mov.b64 %0, {%1, %2};" : "=l"(d) : "f"(x), "f"(x));
    return d;
}
__device__ __forceinline__ void unpack2(unsigned long long v, float& lo, float& hi) {
    asm("mov.b64 {%0, %1}, %2;" : "=f"(lo), "=f"(hi) : "l"(v));
}

// ---------------- vd = W_dst @ att_dst : warp per output ----------------
__global__ void k_vd(const float* __restrict__ Wd, const float* __restrict__ attd) {
    int w = (blockIdx.x * 256 + threadIdx.x) >> 5;
    int lane = threadIdx.x & 31;
    if (w >= Hh) return;
    float4 a = *(const float4*)&Wd[w * Hh + lane * 4];
    float4 u = *(const float4*)&attd[lane * 4];
    float s = a.x * u.x + a.y * u.y + a.z * u.z + a.w * u.w;
    #pragma unroll
    for (int o = 16; o; o >>= 1) s += __shfl_xor_sync(0xffffffffu, s, o);
    if (lane == 0) g_vd[w] = s;
}

// ---------------- GEMM: g_xs = A @ W   (A: [N,128] fp32, W: [128,128]) ----------
// 64 rows x 128 cols per 256-thread block. W + x-tile in SMEM, FFMA2 accumulators.
#define GEMM_SMEM ((128 * 128 + 64 * 132) * 4)
__global__ __launch_bounds__(256) void k_gemm(const float* __restrict__ Aext,
                                              int use_h,
                                              const float* __restrict__ Wg) {
    extern __shared__ float sm[];
    float* Wsm = sm;              // 128*128
    float* Xsm = sm + 128 * 128;  // 64 * 132 (padded)
    const int XS = 132;
    const float* A = use_h ? (const float*)g_h : Aext;
    int t = threadIdx.x;

    #pragma unroll
    for (int i = 0; i < 16; i++) {
        int idx = (t + i * 256) * 4;
        *(float4*)&Wsm[idx] = *(const float4*)&Wg[idx];
    }
    int row0 = blockIdx.x * 64;
    #pragma unroll
    for (int i = 0; i < 8; i++) {
        int idx = t + i * 256;            // 0..2047
        int r = idx >> 5, c4 = idx & 31;
        float4 v = make_float4(0.f, 0.f, 0.f, 0.f);
        int gr = row0 + r;
        if (gr < Nn) v = *(const float4*)&A[(size_t)gr * 128 + c4 * 4];
        *(float4*)&Xsm[r * XS + c4 * 4] = v;
    }
    __syncthreads();

    int tx = t & 15, ty = t >> 4;
    const float* xbase = &Xsm[ty * 4 * XS];
    const float* wbase = &Wsm[tx * 8];

    unsigned long long acc[4][4];
    #pragma unroll
    for (int i = 0; i < 4; i++)
        #pragma unroll
        for (int p = 0; p < 4; p++) acc[i][p] = 0ull;

    #pragma unroll 8
    for (int k = 0; k < 128; k++) {
        ulonglong2 w01 = *(const ulonglong2*)&wbase[k * 128];
        ulonglong2 w23 = *(const ulonglong2*)&wbase[k * 128 + 4];
        unsigned long long wp0 = w01.x, wp1 = w01.y, wp2 = w23.x, wp3 = w23.y;
        #pragma unroll
        for (int i = 0; i < 4; i++) {
            unsigned long long xp = pack2(xbase[i * XS + k]);
            acc[i][0] = fma2(xp, wp0, acc[i][0]);
            acc[i][1] = fma2(xp, wp1, acc[i][1]);
            acc[i][2] = fma2(xp, wp2, acc[i][2]);
            acc[i][3] = fma2(xp, wp3, acc[i][3]);
        }
    }

    #pragma unroll
    for (int i = 0; i < 4; i++) {
        int gr = row0 + ty * 4 + i;
        if (gr < Nn) {
            float o[8];
            #pragma unroll
            for (int p = 0; p < 4; p++) unpack2(acc[i][p], o[2 * p], o[2 * p + 1]);
            float* dstp = &g_xs[(size_t)gr * 128 + tx * 8];
            *(float4*)&dstp[0] = make_float4(o[0], o[1], o[2], o[3]);
            *(float4*)&dstp[4] = make_float4(o[4], o[5], o[6], o[7]);
        }
    }
}

// ---------------- a_s = xs @ att_src ; a_d = in @ vd : warp per row ----------
__global__ __launch_bounds__(256) void k_rowdot(const float* __restrict__ inext,
                                                int use_h,
                                                const float* __restrict__ atts) {
    int t = blockIdx.x * 256 + threadIdx.x;
    int w = t >> 5, lane = t & 31;
    if (w >= Nn) return;
    const float* in = use_h ? (const float*)g_h : inext;
    float4 a = *(const float4*)&g_xs[(size_t)w * 128 + lane * 4];
    float4 u = *(const float4*)&atts[lane * 4];
    float s1 = a.x * u.x + a.y * u.y + a.z * u.z + a.w * u.w;
    float4 b = *(const float4*)&in[(size_t)w * 128 + lane * 4];
    float4 v = *(const float4*)&g_vd[lane * 4];
    float s2 = b.x * v.x + b.y * v.y + b.z * v.z + b.w * v.w;
    #pragma unroll
    for (int o = 16; o; o >>= 1) {
        s1 += __shfl_xor_sync(0xffffffffu, s1, o);
        s2 += __shfl_xor_sync(0xffffffffu, s2, o);
    }
    if (lane == 0) { g_as[w] = s1; g_ad[w] = s2; }
}

// ---------------- zero S + denom ----------------
__global__ void k_zero() {
    int t = blockIdx.x * 256 + threadIdx.x;
    if (t < Nn * 32)
        *(float4*)&g_S[(size_t)t * 4] = make_float4(0.f, 0.f, 0.f, 0.f);
    if (t < Nn) g_denom[t] = 0.f;
}

// ---------------- fused edge kernel: softmax numerator + scatter ----------------
// warp per edge, 4 edges per warp. exp without max-shift (shift-invariant; |e| small).
__global__ __launch_bounds__(256) void k_edge(const int* __restrict__ src,
                                              const int* __restrict__ dst) {
    int wid = (blockIdx.x * 256 + threadIdx.x) >> 5;
    int lane = threadIdx.x & 31;
    int e0 = wid * 4;
    #pragma unroll
    for (int j = 0; j < 4; j++) {
        int e = e0 + j;                  // grid sized so e < Ee always
        int s = src[e], d = dst[e];
        float t = g_as[s] + g_ad[d];
        t = t > 0.f ? t : 0.2f * t;      // leaky_relu(0.2)
        float ex = expf(t);
        if (lane == 0) atomicAdd(&g_denom[d], ex);
        float4 v = *(const float4*)&g_xs[(size_t)s * 128 + lane * 4];
        float* p = &g_S[(size_t)d * 128 + lane * 4];
        asm volatile("red.global.add.v4.f32 [%0], {%1,%2,%3,%4};"
                     :: "l"(p), "f"(v.x * ex), "f"(v.y * ex),
                        "f"(v.z * ex), "f"(v.w * ex)
                     : "memory");
    }
}

// ---------------- node epilogue: h = relu(S/(denom+eps) + bias) ----------------
__global__ void k_node(const float* __restrict__ bias) {
    int t = blockIdx.x * 256 + threadIdx.x;
    if (t >= Nn * 32) return;
    int n = t >> 5, j = t & 31;
    float inv = 1.0f / (g_denom[n] + 1e-16f);
    float4 s = *(const float4*)&g_S[(size_t)t * 4];
    float4 b = *(const float4*)&bias[j * 4];
    float4 o;
    o.x = fmaxf(fmaf(s.x, inv, b.x), 0.f);
    o.y = fmaxf(fmaf(s.y, inv, b.y), 0.f);
    o.z = fmaxf(fmaf(s.z, inv, b.z), 0.f);
    o.w = fmaxf(fmaf(s.w, inv, b.w), 0.f);
    *(float4*)&g_h[(size_t)t * 4] = o;
}

// ---------------- final projection: out = h @ Wl + bl  (O=2) ----------------
__global__ __launch_bounds__(256) void k_final(const float* __restrict__ Wl,
                                               const float* __restrict__ bl,
                                               float* __restrict__ out) {
    __shared__ float wl[256];
    wl[threadIdx.x] = Wl[threadIdx.x];
    __syncthreads();
    int t = blockIdx.x * 256 + threadIdx.x;
    int w = t >> 5, lane = t & 31;
    if (w >= Nn) return;
    float4 v = *(const float4*)&g_h[(size_t)w * 128 + lane * 4];
    int h0 = lane * 4;
    float s0 = v.x * wl[h0 * 2 + 0] + v.y * wl[h0 * 2 + 2] +
               v.z * wl[h0 * 2 + 4] + v.w * wl[h0 * 2 + 6];
    float s1 = v.x * wl[h0 * 2 + 1] + v.y * wl[h0 * 2 + 3] +
               v.z * wl[h0 * 2 + 5] + v.w * wl[h0 * 2 + 7];
    #pragma unroll
    for (int o = 16; o; o >>= 1) {
        s0 += __shfl_xor_sync(0xffffffffu, s0, o);
        s1 += __shfl_xor_sync(0xffffffffu, s1, o);
    }
    if (lane == 0) {
        out[w * 2 + 0] = s0 + bl[0];
        out[w * 2 + 1] = s1 + bl[1];
    }
}

// ---------------- launch ----------------
extern "C" void kernel_launch(void* const* d_in, const int* in_sizes, int n_in,
                              void* d_out, int out_size) {
    const float* x   = (const float*)d_in[0];
    const int*   ei  = (const int*)d_in[1];
    const float* W1s = (const float*)d_in[2];
    const float* W1d = (const float*)d_in[3];
    const float* a1s = (const float*)d_in[4];
    const float* a1d = (const float*)d_in[5];
    const float* b1  = (const float*)d_in[6];
    const float* W2s = (const float*)d_in[7];
    const float* W2d = (const float*)d_in[8];
    const float* a2s = (const float*)d_in[9];
    const float* a2d = (const float*)d_in[10];
    const float* b2  = (const float*)d_in[11];
    const float* Wl  = (const float*)d_in[12];
    const float* bl  = (const float*)d_in[13];
    float* out = (float*)d_out;
    const int* src = ei;
    const int* dst = ei + Ee;

    cudaFuncSetAttribute(k_gemm, cudaFuncAttributeMaxDynamicSharedMemorySize,
                         GEMM_SMEM);

    const int GB   = (Nn + 63) / 64;          // gemm blocks: 1563
    const int RB   = (Nn * 32 + 255) / 256;   // warp-per-row / elem kernels: 12500
    const int EB   = Ee / (8 * 4);            // edge blocks: 50000 (exact)

    // ---- layer 1 ----
    k_vd    <<<16, 256>>>(W1d, a1d);
    k_gemm  <<<GB, 256, GEMM_SMEM>>>(x, 0, W1s);
    k_rowdot<<<RB, 256>>>(x, 0, a1s);
    k_zero  <<<RB, 256>>>();
    k_edge  <<<EB, 256>>>(src, dst);
    k_node  <<<RB, 256>>>(b1);

    // ---- layer 2 ----
    k_vd    <<<16, 256>>>(W2d, a2d);
    k_gemm  <<<GB, 256, GEMM_SMEM>>>(nullptr, 1, W2s);
    k_rowdot<<<RB, 256>>>(nullptr, 1, a2s);
    k_zero  <<<RB, 256>>>();
    k_edge  <<<EB, 256>>>(src, dst);
    k_node  <<<RB, 256>>>(b2);

    // ---- final linear ----
    k_final <<<RB, 256>>>(Wl, bl, out);
}